// round 14
// baseline (speedup 1.0000x reference)
#include <cuda_runtime.h>
#include <cuda_fp16.h>
#include <stdint.h>
#include <math.h>

#define TT   2048
#define HIDN 2048
#define NH   32
#define NKV  8
#define DH   64
#define GRP  4
#define QSCALE 0.1803368801111204f   // (1/8) * log2(e)

// half operands
__device__ __half g_xh[TT * HIDN];
__device__ __half g_wqh[NH * DH * HIDN];
__device__ __half g_wkh[NKV * DH * HIDN];
__device__ __half g_wvh[NKV * DH * HIDN];
__device__ __half g_woh[HIDN * NH * DH];
__device__ __half g_qh[TT * NH * DH];            // rope'd, pre-scaled by QSCALE
__device__ __half g_kh[TT * NKV * DH];           // rope'd
__device__ __half g_vt[NKV * DH * TT];           // V transposed: [kvh][d][t]
__device__ __half g_atth[TT * NH * DH];          // attention output (half)

__device__ __forceinline__ uint32_t pack_half2(float lo, float hi) {
    uint32_t r;
    asm("cvt.rn.f16x2.f32 %0, %1, %2;" : "=r"(r) : "f"(hi), "f"(lo));
    return r;
}

__device__ __forceinline__ float ex2(float x) {
    float r;
    asm("ex2.approx.ftz.f32 %0, %1;" : "=f"(r) : "f"(x));
    return r;
}

__device__ __forceinline__ void mma_fp16(float* c,
                                         uint32_t a0, uint32_t a1, uint32_t a2, uint32_t a3,
                                         uint32_t b0, uint32_t b1) {
    asm volatile(
        "mma.sync.aligned.m16n8k16.row.col.f32.f16.f16.f32 "
        "{%0,%1,%2,%3},{%4,%5,%6,%7},{%8,%9},{%0,%1,%2,%3};"
        : "+f"(c[0]), "+f"(c[1]), "+f"(c[2]), "+f"(c[3])
        : "r"(a0), "r"(a1), "r"(a2), "r"(a3), "r"(b0), "r"(b1));
}

__device__ __forceinline__ void ldsm4(uint32_t& r0, uint32_t& r1,
                                      uint32_t& r2, uint32_t& r3, uint32_t addr) {
    asm volatile("ldmatrix.sync.aligned.m8n8.x4.shared.b16 {%0,%1,%2,%3}, [%4];"
                 : "=r"(r0), "=r"(r1), "=r"(r2), "=r"(r3) : "r"(addr));
}

#define CP_ASYNC16(dst, src) \
    asm volatile("cp.async.ca.shared.global [%0], [%1], 16;" :: "r"(dst), "l"(src) : "memory")
#define CP_COMMIT() asm volatile("cp.async.commit_group;" ::: "memory")
#define CP_WAIT(n)  asm volatile("cp.async.wait_group %0;" :: "n"(n) : "memory")

// ---------------------------------------------------------------------------
// fp32 -> fp16 conversion, 5 tensors in one launch (grid.y selects tensor)
// ---------------------------------------------------------------------------
__global__ void __launch_bounds__(256) tohalf_kernel(const float* x, const float* wq,
                                                     const float* wk, const float* wv,
                                                     const float* wo) {
    const float* src;
    __half* dst;
    int n;
    switch (blockIdx.y) {
        case 0: src = x;  dst = g_xh;  n = TT * HIDN;        break;
        case 1: src = wq; dst = g_wqh; n = NH * DH * HIDN;   break;
        case 2: src = wk; dst = g_wkh; n = NKV * DH * HIDN;  break;
        case 3: src = wv; dst = g_wvh; n = NKV * DH * HIDN;  break;
        default: src = wo; dst = g_woh; n = HIDN * NH * DH;  break;
    }
    int stride = gridDim.x * blockDim.x * 8;
    for (int i = (blockIdx.x * blockDim.x + threadIdx.x) * 8; i < n; i += stride) {
        float4 v0 = *(const float4*)(src + i);
        float4 v1 = *(const float4*)(src + i + 4);
        uint4 o = make_uint4(pack_half2(v0.x, v0.y), pack_half2(v0.z, v0.w),
                             pack_half2(v1.x, v1.y), pack_half2(v1.z, v1.w));
        *(uint4*)(dst + i) = o;
    }
}

// ---------------------------------------------------------------------------
// half GEMM with fused epilogues (128x128 tile for qkv).
// MODE 1: rope+QSCALE -> g_qh.  MODE 2: rope -> g_kh.  MODE 3: transpose -> g_vt.
// ---------------------------------------------------------------------------
#define STW 36
#define HSLAB (128 * STW)
#define GEMM_SMEM (4 * HSLAB * (int)sizeof(uint32_t))
#define SST 132

template <int MODE>
__device__ __forceinline__ void gemm_body(const __half* __restrict__ A,
                                          const __half* __restrict__ B,
                                          int K, int row0, int col0,
                                          uint32_t* __restrict__ sm,
                                          const float* __restrict__ cosb,
                                          const float* __restrict__ sinb) {
    const int tid = threadIdx.x;
    const int wid = tid >> 5, lane = tid & 31;
    const int g = lane >> 2, t = lane & 3;
    const int wm = (wid >> 2) * 64;
    const int wn = (wid & 3) * 32;

    const int rA = ((lane >> 3) & 1) * 8 + (lane & 7);
    const int cA = ((lane >> 4) & 1) * 4;
    const int rB = ((lane >> 4) & 1) * 8 + (lane & 7);
    const int cB = ((lane >> 3) & 1) * 4;

    const uint32_t smb = (uint32_t)__cvta_generic_to_shared(sm);

    float acc[4][4][4];
#pragma unroll
    for (int i = 0; i < 4; i++)
#pragma unroll
        for (int j = 0; j < 4; j++)
#pragma unroll
            for (int q = 0; q < 4; q++) acc[i][j][q] = 0.f;

#define GPREF(s_, buf_) do {                                                     \
    const int kk_ = (s_) * 64;                                                   \
    _Pragma("unroll")                                                            \
    for (int i_ = 0; i_ < 4; i_++) {                                             \
        int e_ = tid + i_ * 256;                                                 \
        int r_ = e_ >> 3, ch_ = e_ & 7;                                          \
        uint32_t ad_ = smb + (uint32_t)((((buf_) * HSLAB) + r_ * STW + ch_ * 4) * 4); \
        CP_ASYNC16(ad_, A + (size_t)(row0 + r_) * K + kk_ + ch_ * 8);            \
        uint32_t bd_ = smb + (uint32_t)((((2 + (buf_)) * HSLAB) + r_ * STW + ch_ * 4) * 4); \
        CP_ASYNC16(bd_, B + (size_t)(col0 + r_) * K + kk_ + ch_ * 8);            \
    }                                                                            \
    CP_COMMIT();                                                                 \
} while (0)

    const int nslab = K >> 6;
    GPREF(0, 0);

    for (int s = 0; s < nslab; s++) {
        const int buf = s & 1;
        if (s + 1 < nslab) {
            GPREF(s + 1, buf ^ 1);
            CP_WAIT(1);
        } else {
            CP_WAIT(0);
        }
        __syncthreads();

        const uint32_t Ab = smb + (uint32_t)(buf * HSLAB * 4);
        const uint32_t Bb = smb + (uint32_t)((2 + buf) * HSLAB * 4);

#pragma unroll
        for (int ks = 0; ks < 4; ks++) {
            const int kk2 = ks * 8;
            uint32_t af[4][4], bf[4][2];
#pragma unroll
            for (int mi = 0; mi < 4; mi++) {
                uint32_t addr = Ab + (uint32_t)(((wm + mi * 16 + rA) * STW + kk2 + cA) * 4);
                ldsm4(af[mi][0], af[mi][1], af[mi][2], af[mi][3], addr);
            }
#pragma unroll
            for (int njp = 0; njp < 2; njp++) {
                uint32_t addr = Bb + (uint32_t)(((wn + njp * 16 + rB) * STW + kk2 + cB) * 4);
                ldsm4(bf[2 * njp][0], bf[2 * njp][1], bf[2 * njp + 1][0], bf[2 * njp + 1][1], addr);
            }
#pragma unroll
            for (int mi = 0; mi < 4; mi++)
#pragma unroll
                for (int nj = 0; nj < 4; nj++)
                    mma_fp16(acc[mi][nj], af[mi][0], af[mi][1], af[mi][2], af[mi][3],
                             bf[nj][0], bf[nj][1]);
        }
        __syncthreads();
    }
#undef GPREF

    if (MODE == 3) {
#pragma unroll
        for (int mi = 0; mi < 4; mi++)
#pragma unroll
            for (int nj = 0; nj < 4; nj++) {
                int time0 = row0 + wm + mi * 16 + g;
                int c = col0 + wn + nj * 8 + 2 * t;
                g_vt[(size_t)c * TT + time0]           = __float2half(acc[mi][nj][0]);
                g_vt[(size_t)(c + 1) * TT + time0]     = __float2half(acc[mi][nj][1]);
                g_vt[(size_t)c * TT + time0 + 8]       = __float2half(acc[mi][nj][2]);
                g_vt[(size_t)(c + 1) * TT + time0 + 8] = __float2half(acc[mi][nj][3]);
            }
    } else {
        float* smf = (float*)sm;
#pragma unroll
        for (int mi = 0; mi < 4; mi++)
#pragma unroll
            for (int nj = 0; nj < 4; nj++) {
                int r = wm + mi * 16 + g;
                int c = wn + nj * 8 + 2 * t;
                *(float2*)&smf[r * SST + c]       = make_float2(acc[mi][nj][0], acc[mi][nj][1]);
                *(float2*)&smf[(r + 8) * SST + c] = make_float2(acc[mi][nj][2], acc[mi][nj][3]);
            }
        __syncthreads();
        const float sc = (MODE == 1) ? QSCALE : 1.0f;
        __half* dst = (MODE == 1) ? g_qh : g_kh;
        const int rowstride = (MODE == 1) ? (NH * DH) : (NKV * DH);
#pragma unroll
        for (int i = 0; i < 16; i++) {
            int e = tid + i * 256;
            int d2 = (e & 15) * 2;
            int head = (e >> 4) & 1;
            int r = e >> 5;
            int cb = head * 64 + d2;
            float2 x1 = *(float2*)&smf[r * SST + cb];
            float2 x2 = *(float2*)&smf[r * SST + cb + 32];
            float2 cc = *(const float2*)&cosb[(size_t)(row0 + r) * DH + d2];
            float2 ss = *(const float2*)&sinb[(size_t)(row0 + r) * DH + d2];
            float o1a = (x1.x * cc.x - x2.x * ss.x) * sc;
            float o1b = (x1.y * cc.y - x2.y * ss.y) * sc;
            float o2a = (x2.x * cc.x + x1.x * ss.x) * sc;
            float o2b = (x2.y * cc.y + x1.y * ss.y) * sc;
            size_t base = (size_t)(row0 + r) * rowstride + col0 + cb;
            *(uint32_t*)&dst[base]      = pack_half2(o1a, o1b);
            *(uint32_t*)&dst[base + 32] = pack_half2(o2a, o2b);
        }
    }
}

__global__ void __launch_bounds__(256, 2) qkv_gemm(const float* __restrict__ cosb,
                                                   const float* __restrict__ sinb) {
    extern __shared__ uint32_t sm[];
    int bx = blockIdx.x;
    int row0 = blockIdx.y * 128;
    if (bx < 16)
        gemm_body<1>(g_xh, g_wqh, HIDN, row0, bx * 128,        sm, cosb, sinb);
    else if (bx < 20)
        gemm_body<2>(g_xh, g_wkh, HIDN, row0, (bx - 16) * 128, sm, cosb, sinb);
    else
        gemm_body<3>(g_xh, g_wvh, HIDN, row0, (bx - 20) * 128, sm, cosb, sinb);
}

// ---------------------------------------------------------------------------
// o_gemm: 128x256 CTA tile, warp tile 64x64, cp.async double-buffered.
// ---------------------------------------------------------------------------
#define HSLAB_A (128 * STW)
#define HSLAB_B (256 * STW)
#define OGEMM_SMEM ((2 * HSLAB_A + 2 * HSLAB_B) * (int)sizeof(uint32_t))

__global__ void __launch_bounds__(256, 1) o_gemm(float* __restrict__ C) {
    extern __shared__ uint32_t sm[];
    const __half* __restrict__ A = g_atth;
    const __half* __restrict__ B = g_woh;
    const int N = HIDN, K = NH * DH;
    const int row0 = blockIdx.y * 128;
    const int col0 = blockIdx.x * 256;

    const int tid = threadIdx.x;
    const int wid = tid >> 5, lane = tid & 31;
    const int g = lane >> 2, t = lane & 3;
    const int wm = (wid >> 2) * 64;
    const int wn = (wid & 3) * 64;

    const int rA = ((lane >> 3) & 1) * 8 + (lane & 7);
    const int cA = ((lane >> 4) & 1) * 4;
    const int rB = ((lane >> 4) & 1) * 8 + (lane & 7);
    const int cB = ((lane >> 3) & 1) * 4;

    const uint32_t smb = (uint32_t)__cvta_generic_to_shared(sm);
    const uint32_t Boff = (uint32_t)(2 * HSLAB_A * 4);

    float acc[4][8][4];
#pragma unroll
    for (int i = 0; i < 4; i++)
#pragma unroll
        for (int j = 0; j < 8; j++)
#pragma unroll
            for (int q = 0; q < 4; q++) acc[i][j][q] = 0.f;

#define OPREF(s_, buf_) do {                                                     \
    const int kk_ = (s_) * 64;                                                   \
    _Pragma("unroll")                                                            \
    for (int i_ = 0; i_ < 4; i_++) {                                             \
        int e_ = tid + i_ * 256;                                                 \
        int r_ = e_ >> 3, ch_ = e_ & 7;                                          \
        uint32_t ad_ = smb + (uint32_t)((((buf_) * HSLAB_A) + r_ * STW + ch_ * 4) * 4); \
        CP_ASYNC16(ad_, A + (size_t)(row0 + r_) * K + kk_ + ch_ * 8);            \
    }                                                                            \
    _Pragma("unroll")                                                            \
    for (int i_ = 0; i_ < 8; i_++) {                                             \
        int e_ = tid + i_ * 256;                                                 \
        int r_ = e_ >> 3, ch_ = e_ & 7;                                          \
        uint32_t bd_ = smb + Boff + (uint32_t)((((buf_) * HSLAB_B) + r_ * STW + ch_ * 4) * 4); \
        CP_ASYNC16(bd_, B + (size_t)(col0 + r_) * K + kk_ + ch_ * 8);            \
    }                                                                            \
    CP_COMMIT();                                                                 \
} while (0)

    const int nslab = K >> 6;
    OPREF(0, 0);

    for (int s = 0; s < nslab; s++) {
        const int buf = s & 1;
        if (s + 1 < nslab) {
            OPREF(s + 1, buf ^ 1);
            CP_WAIT(1);
        } else {
            CP_WAIT(0);
        }
        __syncthreads();

        const uint32_t Ab = smb + (uint32_t)(buf * HSLAB_A * 4);
        const uint32_t Bb = smb + Boff + (uint32_t)(buf * HSLAB_B * 4);

#pragma unroll
        for (int ks = 0; ks < 4; ks++) {
            const int kk2 = ks * 8;
            uint32_t af[4][4], bf[8][2];
#pragma unroll
            for (int mi = 0; mi < 4; mi++) {
                uint32_t addr = Ab + (uint32_t)(((wm + mi * 16 + rA) * STW + kk2 + cA) * 4);
                ldsm4(af[mi][0], af[mi][1], af[mi][2], af[mi][3], addr);
            }
#pragma unroll
            for (int njp = 0; njp < 4; njp++) {
                uint32_t addr = Bb + (uint32_t)(((wn + njp * 16 + rB) * STW + kk2 + cB) * 4);
                ldsm4(bf[2 * njp][0], bf[2 * njp][1], bf[2 * njp + 1][0], bf[2 * njp + 1][1], addr);
            }
#pragma unroll
            for (int mi = 0; mi < 4; mi++)
#pragma unroll
                for (int nj = 0; nj < 8; nj++)
                    mma_fp16(acc[mi][nj], af[mi][0], af[mi][1], af[mi][2], af[mi][3],
                             bf[nj][0], bf[nj][1]);
        }
        __syncthreads();
    }
#undef OPREF

#pragma unroll
    for (int mi = 0; mi < 4; mi++)
#pragma unroll
        for (int nj = 0; nj < 8; nj++) {
            int r = row0 + wm + mi * 16 + g;
            int c = col0 + wn + nj * 8 + 2 * t;
            *(float2*)(C + (size_t)r * N + c)       = make_float2(acc[mi][nj][0], acc[mi][nj][1]);
            *(float2*)(C + (size_t)(r + 8) * N + c) = make_float2(acc[mi][nj][2], acc[mi][nj][3]);
        }
}

// ---------------------------------------------------------------------------
// Flash attention: 256 q-rows per CTA (two 128-row halves sharing K/V tiles),
// fp16 MMA, register-resident P, shared-ldsm joint loops, 4-stage cp.async.
// 256 threads = 8 warps; warp owns 16 rows of each half.
// ---------------------------------------------------------------------------
#define KP2 36
#define TILEW (64 * KP2)
#define NSTG 4
#define ATTN_SMEM (2 * NSTG * TILEW * (int)sizeof(uint32_t))

__global__ void __launch_bounds__(256, 1) attn_kernel() {
    extern __shared__ uint32_t abuf[];
    uint32_t* Ks = abuf;
    uint32_t* Vs = abuf + NSTG * TILEW;

    const int tid = threadIdx.x;
    const int wid = tid >> 5, lane = tid & 31;
    const int g = lane >> 2, t = lane & 3;
    const int wm = wid * 16;
    const int h = blockIdx.y;
    const int kvh = h / GRP;
    const int bx = gridDim.x - 1 - blockIdx.x;   // heavy CTAs first
    const int m0 = bx * 256;

    const int rB = ((lane >> 4) & 1) * 8 + (lane & 7);
    const int cB = ((lane >> 3) & 1) * 4;
    const uint32_t ksb = (uint32_t)__cvta_generic_to_shared(Ks);
    const uint32_t vsb = (uint32_t)__cvta_generic_to_shared(Vs);

    const int pr0 = tid >> 3,          pc0 = tid & 7;
    const int pr1 = (tid + 256) >> 3,  pc1 = tid & 7;
    const __half* kbase = &g_kh[(size_t)kvh * DH];
    const __half* vbase = &g_vt[(size_t)kvh * DH * TT];

#define PREFETCH(jt_, buf_) do {                                               \
    const int nn = (jt_) * 64;                                                 \
    uint32_t kd = ksb + (uint32_t)(((buf_) * TILEW + pr0 * KP2 + pc0 * 4) * 4);\
    CP_ASYNC16(kd, kbase + (size_t)(nn + pr0) * (NKV * DH) + pc0 * 8);         \
    kd = ksb + (uint32_t)(((buf_) * TILEW + pr1 * KP2 + pc1 * 4) * 4);         \
    CP_ASYNC16(kd, kbase + (size_t)(nn + pr1) * (NKV * DH) + pc1 * 8);         \
    uint32_t vd = vsb + (uint32_t)(((buf_) * TILEW + pr0 * KP2 + pc0 * 4) * 4);\
    CP_ASYNC16(vd, vbase + (size_t)pr0 * TT + nn + pc0 * 8);                   \
    vd = vsb + (uint32_t)(((buf_) * TILEW + pr1 * KP2 + pc1 * 4) * 4);         \
    CP_ASYNC16(vd, vbase + (size_t)pr1 * TT + nn + pc1 * 8);                   \
    CP_COMMIT();                                                               \
} while (0)

    // Fragment rows: half0 = r0/r1, half1 = r2/r3
    const int r0 = m0 + wm + g, r1 = r0 + 8;
    const int r2 = r0 + 128,    r3 = r1 + 128;
    uint32_t qf0[4][4], qf1[4][4];
    {
        const __half* qa = &g_qh[(size_t)r0 * (NH * DH) + h * DH];
        const __half* qb = &g_qh[(size_t)r1 * (NH * DH) + h * DH];
        const __half* qc = &g_qh[(size_t)r2 * (NH * DH) + h * DH];
        const __half* qd = &g_qh[(size_t)r3 * (NH * DH) + h * DH];
#pragma unroll
        for (int ks = 0; ks < 4; ks++) {
            qf0[ks][0] = *(const uint32_t*)(qa + ks * 16 + 2 * t);
            qf0[ks][1] = *(const uint32_t*)(qb + ks * 16 + 2 * t);
            qf0[ks][2] = *(const uint32_t*)(qa + ks * 16 + 8 + 2 * t);
            qf0[ks][3] = *(const uint32_t*)(qb + ks * 16 + 8 + 2 * t);
            qf1[ks][0] = *(const uint32_t*)(qc + ks * 16 + 2 * t);
            qf1[ks][1] = *(const uint32_t*)(qd + ks * 16 + 2 * t);
            qf1[ks][2] = *(const uint32_t*)(qc + ks * 16 + 8 + 2 * t);
            qf1[ks][3] = *(const uint32_t*)(qd + ks * 16 + 8 + 2 * t);
        }
    }

    float mA0 = -1e30f, mA1 = -1e30f, lA0 = 0.f, lA1 = 0.f;   // half0
    float mB0 = -1e30f, mB1 = -1e30f, lB0 = 0.f, lB1 = 0.f;   // half1
    float o0[8][4], o1[8][4];
#pragma unroll
    for (int j = 0; j < 8; j++)
#pragma unroll
        for (int q = 0; q < 4; q++) { o0[j][q] = 0.f; o1[j][q] = 0.f; }

    const int ntiles = 4 * bx + 4;
    const int h0lim = 4 * bx + 2;       // half0 active while jt < h0lim

#pragma unroll 1
    for (int p = 0; p < NSTG - 1 && p < ntiles; p++) PREFETCH(p, p);

    int buf = 0;
#pragma unroll 1
    for (int jt = 0; jt < ntiles; jt++) {
        const int n0 = jt * 64;
        if (jt + 3 < ntiles) {
            int pb = buf + 3; if (pb >= NSTG) pb -= NSTG;
            PREFETCH(jt + 3, pb);
            CP_WAIT(3);
        } else if (jt + 2 < ntiles) {
            CP_WAIT(2);
        } else if (jt + 1 < ntiles) {
            CP_WAIT(1);
        } else {
            CP_WAIT(0);
        }
        __syncthreads();

        const uint32_t kb = ksb + (uint32_t)(buf * TILEW * 4);
        const uint32_t vb = vsb + (uint32_t)(buf * TILEW * 4);
        const bool h0act = (jt < h0lim);

        float s0[8][4], s1[8][4];
#pragma unroll
        for (int j = 0; j < 8; j++)
#pragma unroll
            for (int q = 0; q < 4; q++) s1[j][q] = 0.f;

        if (h0act) {
#pragma unroll
            for (int j = 0; j < 8; j++)
#pragma unroll
                for (int q = 0; q < 4; q++) s0[j][q] = 0.f;
            // Joint S: one ldsm feeds 4 MMAs
#pragma unroll
            for (int ks = 0; ks < 4; ks++) {
                const int kk2 = ks * 8;
#pragma unroll
                for (int njp = 0; njp < 4; njp++) {
                    uint32_t b0, b1, b2, b3;
                    uint32_t addr = kb + (uint32_t)(((njp * 16 + rB) * KP2 + kk2 + cB) * 4);
                    ldsm4(b0, b1, b2, b3, addr);
                    mma_fp16(s0[2 * njp],     qf0[ks][0], qf0[ks][1], qf0[ks][2], qf0[ks][3], b0, b1);
                    mma_fp16(s0[2 * njp + 1], qf0[ks][0], qf0[ks][1], qf0[ks][2], qf0[ks][3], b2, b3);
                    mma_fp16(s1[2 * njp],     qf1[ks][0], qf1[ks][1], qf1[ks][2], qf1[ks][3], b0, b1);
                    mma_fp16(s1[2 * njp + 1], qf1[ks][0], qf1[ks][1], qf1[ks][2], qf1[ks][3], b2, b3);
                }
            }
            // half0 mask (tiles jt = 4bx, 4bx+1); half1 never masked here
            if (jt >= 4 * bx) {
#pragma unroll
                for (int nj = 0; nj < 8; nj++) {
                    int c0 = n0 + nj * 8 + 2 * t;
                    if (c0     > r0) s0[nj][0] = -1e30f;
                    if (c0 + 1 > r0) s0[nj][1] = -1e30f;
                    if (c0     > r1) s0[nj][2] = -1e30f;
                    if (c0 + 1 > r1) s0[nj][3] = -1e30f;
                }
            }
        } else {
#pragma unroll
            for (int ks = 0; ks < 4; ks++) {
                const int kk2 = ks * 8;
#pragma unroll
                for (int njp = 0; njp < 4; njp++) {
                    uint32_t b0, b1, b2, b3;
                    uint32_t addr = kb + (uint32_t)(((njp * 16 + rB) * KP2 + kk2 + cB) * 4);
                    ldsm4(b0, b1, b2, b3, addr);
                    mma_fp16(s1[2 * njp],     qf1[ks][0], qf1[ks][1], qf1[ks][2], qf1[ks][3], b0, b1);
                    mma_fp16(s1[2 * njp + 1], qf1[ks][0], qf1[ks][1], qf1[ks][2], qf1[ks][3], b2, b3);
                }
            }
            // half1 mask (tiles jt = 4bx+2, 4bx+3)
#pragma unroll
            for (int nj = 0; nj < 8; nj++) {
                int c0 = n0 + nj * 8 + 2 * t;
                if (c0     > r2) s1[nj][0] = -1e30f;
                if (c0 + 1 > r2) s1[nj][1] = -1e30f;
                if (c0     > r3) s1[nj][2] = -1e30f;
                if (c0 + 1 > r3) s1[nj][3] = -1e30f;
            }
        }

        // Softmax half0
        if (h0act) {
            float mx0 = -1e30f, mx1 = -1e30f;
#pragma unroll
            for (int nj = 0; nj < 8; nj++) {
                mx0 = fmaxf(mx0, fmaxf(s0[nj][0], s0[nj][1]));
                mx1 = fmaxf(mx1, fmaxf(s0[nj][2], s0[nj][3]));
            }
            mx0 = fmaxf(mx0, __shfl_xor_sync(0xffffffffu, mx0, 1));
            mx0 = fmaxf(mx0, __shfl_xor_sync(0xffffffffu, mx0, 2));
            mx1 = fmaxf(mx1, __shfl_xor_sync(0xffffffffu, mx1, 1));
            mx1 = fmaxf(mx1, __shfl_xor_sync(0xffffffffu, mx1, 2));
            float nm0 = fmaxf(mA0, mx0), nm1 = fmaxf(mA1, mx1);
            float f0 = ex2(mA0 - nm0), f1 = ex2(mA1 - nm1);
            float ps0 = 0.f, ps1 = 0.f;
#pragma unroll
            for (int nj = 0; nj < 8; nj++) {
                s0[nj][0] = ex2(s0[nj][0] - nm0);
                s0[nj][1] = ex2(s0[nj][1] - nm0);
                s0[nj][2] = ex2(s0[nj][2] - nm1);
                s0[nj][3] = ex2(s0[nj][3] - nm1);
                ps0 += s0[nj][0] + s0[nj][1];
                ps1 += s0[nj][2] + s0[nj][3];
            }
            lA0 = lA0 * f0 + ps0; lA1 = lA1 * f1 + ps1;
            mA0 = nm0; mA1 = nm1;
#pragma unroll
            for (int nj = 0; nj < 8; nj++) {
                o0[nj][0] *= f0; o0[nj][1] *= f0;
                o0[nj][2] *= f1; o0[nj][3] *= f1;
            }
        }
        // Softmax half1
        {
            float mx0 = -1e30f, mx1 = -1e30f;
#pragma unroll
            for (int nj = 0; nj < 8; nj++) {
                mx0 = fmaxf(mx0, fmaxf(s1[nj][0], s1[nj][1]));
                mx1 = fmaxf(mx1, fmaxf(s1[nj][2], s1[nj][3]));
            }
            mx0 = fmaxf(mx0, __shfl_xor_sync(0xffffffffu, mx0, 1));
            mx0 = fmaxf(mx0, __shfl_xor_sync(0xffffffffu, mx0, 2));
            mx1 = fmaxf(mx1, __shfl_xor_sync(0xffffffffu, mx1, 1));
            mx1 = fmaxf(mx1, __shfl_xor_sync(0xffffffffu, mx1, 2));
            float nm0 = fmaxf(mB0, mx0), nm1 = fmaxf(mB1, mx1);
            float f0 = ex2(mB0 - nm0), f1 = ex2(mB1 - nm1);
            float ps0 = 0.f, ps1 = 0.f;
#pragma unroll
            for (int nj = 0; nj < 8; nj++) {
                s1[nj][0] = ex2(s1[nj][0] - nm0);
                s1[nj][1] = ex2(s1[nj][1] - nm0);
                s1[nj][2] = ex2(s1[nj][2] - nm1);
                s1[nj][3] = ex2(s1[nj][3] - nm1);
                ps0 += s1[nj][0] + s1[nj][1];
                ps1 += s1[nj][2] + s1[nj][3];
            }
            lB0 = lB0 * f0 + ps0; lB1 = lB1 * f1 + ps1;
            mB0 = nm0; mB1 = nm1;
#pragma unroll
            for (int nj = 0; nj < 8; nj++) {
                o1[nj][0] *= f0; o1[nj][1] *= f0;
                o1[nj][2] *= f1; o1[nj][3] *= f1;
            }
        }

        // PV (joint when half0 active: one V ldsm feeds 4 MMAs)
        if (h0act) {
#pragma unroll
            for (int ks = 0; ks < 4; ks++) {
                uint32_t a00 = pack_half2(s0[2 * ks][0],     s0[2 * ks][1]);
                uint32_t a01 = pack_half2(s0[2 * ks][2],     s0[2 * ks][3]);
                uint32_t a02 = pack_half2(s0[2 * ks + 1][0], s0[2 * ks + 1][1]);
                uint32_t a03 = pack_half2(s0[2 * ks + 1][2], s0[2 * ks + 1][3]);
                uint32_t a10 = pack_half2(s1[2 * ks][0],     s1[2 * ks][1]);
                uint32_t a11 = pack_half2(s1[2 * ks][2],     s1[2 * ks][3]);
                uint32_t a12 = pack_half2(s1[2 * ks + 1][0], s1[2 * ks + 1][1]);
                uint32_t a13 = pack_half2(s1[2 * ks + 1][2], s1[2 * ks + 1][3]);
                const int kk2 = ks * 8;
#pragma unroll
                for (int njp = 0; njp < 4; njp++) {
                    uint32_t b0, b1, b2, b3;
                    uint32_t addr = vb + (uint32_t)(((njp * 16 + rB) * KP2 + kk2 + cB) * 4);
                    ldsm4(b0, b1, b2, b3, addr);
                    mma_fp16(o0[2 * njp],     a00, a01, a02, a03, b0, b1);
                    mma_fp16(o0[2 * njp + 1], a00, a01, a02, a03, b2, b3);
                    mma_fp16(o1[2 * njp],     a10, a11, a12, a13, b0, b1);
                    mma_fp16(o1[2 * njp + 1], a10, a11, a12, a13, b2, b3);
                }
            }
        } else {
#pragma unroll
            for (int ks = 0; ks < 4; ks++) {
                uint32_t a10 = pack_half2(s1[2 * ks][0],     s1[2 * ks][1]);
                uint32_t a11 = pack_half2(s1[2 * ks][2],     s1[2 * ks][3]);
                uint32_t a12 = pack_half2(s1[2 * ks + 1][0], s1[2 * ks + 1][1]);
                uint32_t a13 = pack_half2(s1[2 * ks + 1][2], s1[2 * ks + 1][3]);
                const int kk2 = ks * 8;
#pragma unroll
                for (int njp = 0; njp < 4; njp++) {
                    uint32_t b0, b1, b2, b3;
                    uint32_t addr = vb + (uint32_t)(((njp * 16 + rB) * KP2 + kk2 + cB) * 4);
                    ldsm4(b0, b1, b2, b3, addr);
                    mma_fp16(o1[2 * njp],     a10, a11, a12, a13, b0, b1);
                    mma_fp16(o1[2 * njp + 1], a10, a11, a12, a13, b2, b3);
                }
            }
        }
        __syncthreads();
        if (++buf == NSTG) buf = 0;
    }

    // Final quad reductions and stores (both halves)
    lA0 += __shfl_xor_sync(0xffffffffu, lA0, 1);
    lA0 += __shfl_xor_sync(0xffffffffu, lA0, 2);
    lA1 += __shfl_xor_sync(0xffffffffu, lA1, 1);
    lA1 += __shfl_xor_sync(0xffffffffu, lA1, 2);
    lB0 += __shfl_xor_sync(0xffffffffu, lB0, 1);
    lB0 += __shfl_xor_sync(0xffffffffu, lB0, 2);
    lB1 += __shfl_xor_sync(0xffffffffu, lB1, 1);
    lB1 += __shfl_xor_sync(0xffffffffu, lB1, 2);
    float iA0 = 1.f / lA0, iA1 = 1.f / lA1;
    float iB0 = 1.f / lB0, iB1 = 1.f / lB1;
#pragma unroll
    for (int nj = 0; nj < 8; nj++) {
        int c = nj * 8 + 2 * t;
        *(uint32_t*)&g_atth[(size_t)r0 * (NH * DH) + h * DH + c] =
            pack_half2(o0[nj][0] * iA0, o0[nj][1] * iA0);
        *(uint32_t*)&g_atth[(size_t)r1 * (NH * DH) + h * DH + c] =
            pack_half2(o0[nj][2] * iA1, o0[nj][3] * iA1);
        *(uint32_t*)&g_atth[(size_t)r2 * (NH * DH) + h * DH + c] =
            pack_half2(o1[nj][0] * iB0, o1[nj][1] * iB0);
        *(uint32_t*)&g_atth[(size_t)r3 * (NH * DH) + h * DH + c] =
            pack_half2(o1[nj][2] * iB1, o1[nj][3] * iB1);
    }
#undef PREFETCH
}

// ---------------------------------------------------------------------------
extern "C" void kernel_launch(void* const* d_in, const int* in_sizes, int n_in,
                              void* d_out, int out_size) {
    const float* x    = (const float*)d_in[0];
    const float* cosb = (const float*)d_in[1];
    const float* sinb = (const float*)d_in[2];
    const float* Wq   = (const float*)d_in[4];
    const float* Wk   = (const float*)d_in[5];
    const float* Wv   = (const float*)d_in[6];
    const float* Wo   = (const float*)d_in[7];
    float* out = (float*)d_out;

    cudaFuncSetAttribute(qkv_gemm, cudaFuncAttributeMaxDynamicSharedMemorySize, GEMM_SMEM);
    cudaFuncSetAttribute(o_gemm,   cudaFuncAttributeMaxDynamicSharedMemorySize, OGEMM_SMEM);
    cudaFuncSetAttribute(attn_kernel, cudaFuncAttributeMaxDynamicSharedMemorySize, ATTN_SMEM);

    tohalf_kernel<<<dim3(592, 5), 256>>>(x, Wq, Wk, Wv, Wo);

    qkv_gemm<<<dim3(24, 16), 256, GEMM_SMEM>>>(cosb, sinb);

    attn_kernel<<<dim3(TT / 256, NH), 256, ATTN_SMEM>>>();

    o_gemm<<<dim3(8, 16), 256, OGEMM_SMEM>>>(out);
}

// round 15
// speedup vs baseline: 1.0354x; 1.0354x over previous
#include <cuda_runtime.h>
#include <cuda_fp16.h>
#include <stdint.h>
#include <math.h>

#define TT   2048
#define HIDN 2048
#define NH   32
#define NKV  8
#define DH   64
#define GRP  4
#define QSCALE 0.1803368801111204f   // (1/8) * log2(e)

// half operands
__device__ __half g_xh[TT * HIDN];
__device__ __half g_wqh[NH * DH * HIDN];
__device__ __half g_wkh[NKV * DH * HIDN];
__device__ __half g_wvh[NKV * DH * HIDN];
__device__ __half g_woh[HIDN * NH * DH];
__device__ __half g_qh[TT * NH * DH];            // rope'd, pre-scaled by QSCALE
__device__ __half g_kh[TT * NKV * DH];           // rope'd
__device__ __half g_vt[NKV * DH * TT];           // V transposed: [kvh][d][t]
__device__ __half g_atth[TT * NH * DH];          // attention output (half)

__device__ __forceinline__ uint32_t pack_half2(float lo, float hi) {
    uint32_t r;
    asm("cvt.rn.f16x2.f32 %0, %1, %2;" : "=r"(r) : "f"(hi), "f"(lo));
    return r;
}

__device__ __forceinline__ float ex2(float x) {
    float r;
    asm("ex2.approx.ftz.f32 %0, %1;" : "=f"(r) : "f"(x));
    return r;
}

__device__ __forceinline__ void mma_fp16(float* c,
                                         uint32_t a0, uint32_t a1, uint32_t a2, uint32_t a3,
                                         uint32_t b0, uint32_t b1) {
    asm volatile(
        "mma.sync.aligned.m16n8k16.row.col.f32.f16.f16.f32 "
        "{%0,%1,%2,%3},{%4,%5,%6,%7},{%8,%9},{%0,%1,%2,%3};"
        : "+f"(c[0]), "+f"(c[1]), "+f"(c[2]), "+f"(c[3])
        : "r"(a0), "r"(a1), "r"(a2), "r"(a3), "r"(b0), "r"(b1));
}

__device__ __forceinline__ void ldsm4(uint32_t& r0, uint32_t& r1,
                                      uint32_t& r2, uint32_t& r3, uint32_t addr) {
    asm volatile("ldmatrix.sync.aligned.m8n8.x4.shared.b16 {%0,%1,%2,%3}, [%4];"
                 : "=r"(r0), "=r"(r1), "=r"(r2), "=r"(r3) : "r"(addr));
}

#define CP_ASYNC16(dst, src) \
    asm volatile("cp.async.ca.shared.global [%0], [%1], 16;" :: "r"(dst), "l"(src) : "memory")
#define CP_COMMIT() asm volatile("cp.async.commit_group;" ::: "memory")
#define CP_WAIT(n)  asm volatile("cp.async.wait_group %0;" :: "n"(n) : "memory")

// ---------------------------------------------------------------------------
// fp32 -> fp16 conversion, 5 tensors in one launch (grid.y selects tensor)
// ---------------------------------------------------------------------------
__global__ void __launch_bounds__(256) tohalf_kernel(const float* x, const float* wq,
                                                     const float* wk, const float* wv,
                                                     const float* wo) {
    const float* src;
    __half* dst;
    int n;
    switch (blockIdx.y) {
        case 0: src = x;  dst = g_xh;  n = TT * HIDN;        break;
        case 1: src = wq; dst = g_wqh; n = NH * DH * HIDN;   break;
        case 2: src = wk; dst = g_wkh; n = NKV * DH * HIDN;  break;
        case 3: src = wv; dst = g_wvh; n = NKV * DH * HIDN;  break;
        default: src = wo; dst = g_woh; n = HIDN * NH * DH;  break;
    }
    int stride = gridDim.x * blockDim.x * 8;
    for (int i = (blockIdx.x * blockDim.x + threadIdx.x) * 8; i < n; i += stride) {
        float4 v0 = *(const float4*)(src + i);
        float4 v1 = *(const float4*)(src + i + 4);
        uint4 o = make_uint4(pack_half2(v0.x, v0.y), pack_half2(v0.z, v0.w),
                             pack_half2(v1.x, v1.y), pack_half2(v1.z, v1.w));
        *(uint4*)(dst + i) = o;
    }
}

// ---------------------------------------------------------------------------
// half GEMM with fused epilogues (128x128 tile for qkv).
// MODE 1: rope+QSCALE -> g_qh.  MODE 2: rope -> g_kh.  MODE 3: transpose -> g_vt.
// ---------------------------------------------------------------------------
#define STW 36
#define HSLAB (128 * STW)
#define GEMM_SMEM (4 * HSLAB * (int)sizeof(uint32_t))
#define SST 132

template <int MODE>
__device__ __forceinline__ void gemm_body(const __half* __restrict__ A,
                                          const __half* __restrict__ B,
                                          int K, int row0, int col0,
                                          uint32_t* __restrict__ sm,
                                          const float* __restrict__ cosb,
                                          const float* __restrict__ sinb) {
    const int tid = threadIdx.x;
    const int wid = tid >> 5, lane = tid & 31;
    const int g = lane >> 2, t = lane & 3;
    const int wm = (wid >> 2) * 64;
    const int wn = (wid & 3) * 32;

    const int rA = ((lane >> 3) & 1) * 8 + (lane & 7);
    const int cA = ((lane >> 4) & 1) * 4;
    const int rB = ((lane >> 4) & 1) * 8 + (lane & 7);
    const int cB = ((lane >> 3) & 1) * 4;

    const uint32_t smb = (uint32_t)__cvta_generic_to_shared(sm);

    float acc[4][4][4];
#pragma unroll
    for (int i = 0; i < 4; i++)
#pragma unroll
        for (int j = 0; j < 4; j++)
#pragma unroll
            for (int q = 0; q < 4; q++) acc[i][j][q] = 0.f;

#define GPREF(s_, buf_) do {                                                     \
    const int kk_ = (s_) * 64;                                                   \
    _Pragma("unroll")                                                            \
    for (int i_ = 0; i_ < 4; i_++) {                                             \
        int e_ = tid + i_ * 256;                                                 \
        int r_ = e_ >> 3, ch_ = e_ & 7;                                          \
        uint32_t ad_ = smb + (uint32_t)((((buf_) * HSLAB) + r_ * STW + ch_ * 4) * 4); \
        CP_ASYNC16(ad_, A + (size_t)(row0 + r_) * K + kk_ + ch_ * 8);            \
        uint32_t bd_ = smb + (uint32_t)((((2 + (buf_)) * HSLAB) + r_ * STW + ch_ * 4) * 4); \
        CP_ASYNC16(bd_, B + (size_t)(col0 + r_) * K + kk_ + ch_ * 8);            \
    }                                                                            \
    CP_COMMIT();                                                                 \
} while (0)

    const int nslab = K >> 6;
    GPREF(0, 0);

    for (int s = 0; s < nslab; s++) {
        const int buf = s & 1;
        if (s + 1 < nslab) {
            GPREF(s + 1, buf ^ 1);
            CP_WAIT(1);
        } else {
            CP_WAIT(0);
        }
        __syncthreads();

        const uint32_t Ab = smb + (uint32_t)(buf * HSLAB * 4);
        const uint32_t Bb = smb + (uint32_t)((2 + buf) * HSLAB * 4);

#pragma unroll
        for (int ks = 0; ks < 4; ks++) {
            const int kk2 = ks * 8;
            uint32_t af[4][4], bf[4][2];
#pragma unroll
            for (int mi = 0; mi < 4; mi++) {
                uint32_t addr = Ab + (uint32_t)(((wm + mi * 16 + rA) * STW + kk2 + cA) * 4);
                ldsm4(af[mi][0], af[mi][1], af[mi][2], af[mi][3], addr);
            }
#pragma unroll
            for (int njp = 0; njp < 2; njp++) {
                uint32_t addr = Bb + (uint32_t)(((wn + njp * 16 + rB) * STW + kk2 + cB) * 4);
                ldsm4(bf[2 * njp][0], bf[2 * njp][1], bf[2 * njp + 1][0], bf[2 * njp + 1][1], addr);
            }
#pragma unroll
            for (int mi = 0; mi < 4; mi++)
#pragma unroll
                for (int nj = 0; nj < 4; nj++)
                    mma_fp16(acc[mi][nj], af[mi][0], af[mi][1], af[mi][2], af[mi][3],
                             bf[nj][0], bf[nj][1]);
        }
        __syncthreads();
    }
#undef GPREF

    if (MODE == 3) {
#pragma unroll
        for (int mi = 0; mi < 4; mi++)
#pragma unroll
            for (int nj = 0; nj < 4; nj++) {
                int time0 = row0 + wm + mi * 16 + g;
                int c = col0 + wn + nj * 8 + 2 * t;
                g_vt[(size_t)c * TT + time0]           = __float2half(acc[mi][nj][0]);
                g_vt[(size_t)(c + 1) * TT + time0]     = __float2half(acc[mi][nj][1]);
                g_vt[(size_t)c * TT + time0 + 8]       = __float2half(acc[mi][nj][2]);
                g_vt[(size_t)(c + 1) * TT + time0 + 8] = __float2half(acc[mi][nj][3]);
            }
    } else {
        float* smf = (float*)sm;
#pragma unroll
        for (int mi = 0; mi < 4; mi++)
#pragma unroll
            for (int nj = 0; nj < 4; nj++) {
                int r = wm + mi * 16 + g;
                int c = wn + nj * 8 + 2 * t;
                *(float2*)&smf[r * SST + c]       = make_float2(acc[mi][nj][0], acc[mi][nj][1]);
                *(float2*)&smf[(r + 8) * SST + c] = make_float2(acc[mi][nj][2], acc[mi][nj][3]);
            }
        __syncthreads();
        const float sc = (MODE == 1) ? QSCALE : 1.0f;
        __half* dst = (MODE == 1) ? g_qh : g_kh;
        const int rowstride = (MODE == 1) ? (NH * DH) : (NKV * DH);
#pragma unroll
        for (int i = 0; i < 16; i++) {
            int e = tid + i * 256;
            int d2 = (e & 15) * 2;
            int head = (e >> 4) & 1;
            int r = e >> 5;
            int cb = head * 64 + d2;
            float2 x1 = *(float2*)&smf[r * SST + cb];
            float2 x2 = *(float2*)&smf[r * SST + cb + 32];
            float2 cc = *(const float2*)&cosb[(size_t)(row0 + r) * DH + d2];
            float2 ss = *(const float2*)&sinb[(size_t)(row0 + r) * DH + d2];
            float o1a = (x1.x * cc.x - x2.x * ss.x) * sc;
            float o1b = (x1.y * cc.y - x2.y * ss.y) * sc;
            float o2a = (x2.x * cc.x + x1.x * ss.x) * sc;
            float o2b = (x2.y * cc.y + x1.y * ss.y) * sc;
            size_t base = (size_t)(row0 + r) * rowstride + col0 + cb;
            *(uint32_t*)&dst[base]      = pack_half2(o1a, o1b);
            *(uint32_t*)&dst[base + 32] = pack_half2(o2a, o2b);
        }
    }
}

__global__ void __launch_bounds__(256, 2) qkv_gemm(const float* __restrict__ cosb,
                                                   const float* __restrict__ sinb) {
    extern __shared__ uint32_t sm[];
    int bx = blockIdx.x;
    int row0 = blockIdx.y * 128;
    if (bx < 16)
        gemm_body<1>(g_xh, g_wqh, HIDN, row0, bx * 128,        sm, cosb, sinb);
    else if (bx < 20)
        gemm_body<2>(g_xh, g_wkh, HIDN, row0, (bx - 16) * 128, sm, cosb, sinb);
    else
        gemm_body<3>(g_xh, g_wvh, HIDN, row0, (bx - 20) * 128, sm, cosb, sinb);
}

// ---------------------------------------------------------------------------
// o_gemm: 128x256 CTA tile, warp tile 64x64, 3-stage cp.async pipeline.
// ---------------------------------------------------------------------------
#define HSLAB_A (128 * STW)
#define HSLAB_B (256 * STW)
#define OSTG 3
#define OGEMM_SMEM ((OSTG * HSLAB_A + OSTG * HSLAB_B) * (int)sizeof(uint32_t))

__global__ void __launch_bounds__(256, 1) o_gemm(float* __restrict__ C) {
    extern __shared__ uint32_t sm[];
    const __half* __restrict__ A = g_atth;
    const __half* __restrict__ B = g_woh;
    const int N = HIDN, K = NH * DH;
    const int row0 = blockIdx.y * 128;
    const int col0 = blockIdx.x * 256;

    const int tid = threadIdx.x;
    const int wid = tid >> 5, lane = tid & 31;
    const int g = lane >> 2, t = lane & 3;
    const int wm = (wid >> 2) * 64;
    const int wn = (wid & 3) * 64;

    const int rA = ((lane >> 3) & 1) * 8 + (lane & 7);
    const int cA = ((lane >> 4) & 1) * 4;
    const int rB = ((lane >> 4) & 1) * 8 + (lane & 7);
    const int cB = ((lane >> 3) & 1) * 4;

    const uint32_t smb = (uint32_t)__cvta_generic_to_shared(sm);
    const uint32_t Boff = (uint32_t)(OSTG * HSLAB_A * 4);

    float acc[4][8][4];
#pragma unroll
    for (int i = 0; i < 4; i++)
#pragma unroll
        for (int j = 0; j < 8; j++)
#pragma unroll
            for (int q = 0; q < 4; q++) acc[i][j][q] = 0.f;

#define OPREF(s_, buf_) do {                                                     \
    const int kk_ = (s_) * 64;                                                   \
    _Pragma("unroll")                                                            \
    for (int i_ = 0; i_ < 4; i_++) {                                             \
        int e_ = tid + i_ * 256;                                                 \
        int r_ = e_ >> 3, ch_ = e_ & 7;                                          \
        uint32_t ad_ = smb + (uint32_t)((((buf_) * HSLAB_A) + r_ * STW + ch_ * 4) * 4); \
        CP_ASYNC16(ad_, A + (size_t)(row0 + r_) * K + kk_ + ch_ * 8);            \
    }                                                                            \
    _Pragma("unroll")                                                            \
    for (int i_ = 0; i_ < 8; i_++) {                                             \
        int e_ = tid + i_ * 256;                                                 \
        int r_ = e_ >> 3, ch_ = e_ & 7;                                          \
        uint32_t bd_ = smb + Boff + (uint32_t)((((buf_) * HSLAB_B) + r_ * STW + ch_ * 4) * 4); \
        CP_ASYNC16(bd_, B + (size_t)(col0 + r_) * K + kk_ + ch_ * 8);            \
    }                                                                            \
    CP_COMMIT();                                                                 \
} while (0)

    const int nslab = K >> 6;
    OPREF(0, 0);
    if (nslab > 1) OPREF(1, 1);

    int buf = 0;
#pragma unroll 1
    for (int s = 0; s < nslab; s++) {
        if (s + 2 < nslab) {
            int pb = buf + 2; if (pb >= OSTG) pb -= OSTG;
            OPREF(s + 2, pb);
            CP_WAIT(2);
        } else if (s + 1 < nslab) {
            CP_WAIT(1);
        } else {
            CP_WAIT(0);
        }
        __syncthreads();

        const uint32_t Ab = smb + (uint32_t)(buf * HSLAB_A * 4);
        const uint32_t Bb = smb + Boff + (uint32_t)(buf * HSLAB_B * 4);

#pragma unroll
        for (int ks = 0; ks < 4; ks++) {
            const int kk2 = ks * 8;
            uint32_t af[4][4], bf[8][2];
#pragma unroll
            for (int mi = 0; mi < 4; mi++) {
                uint32_t addr = Ab + (uint32_t)(((wm + mi * 16 + rA) * STW + kk2 + cA) * 4);
                ldsm4(af[mi][0], af[mi][1], af[mi][2], af[mi][3], addr);
            }
#pragma unroll
            for (int njp = 0; njp < 4; njp++) {
                uint32_t addr = Bb + (uint32_t)(((wn + njp * 16 + rB) * STW + kk2 + cB) * 4);
                ldsm4(bf[2 * njp][0], bf[2 * njp][1], bf[2 * njp + 1][0], bf[2 * njp + 1][1], addr);
            }
#pragma unroll
            for (int mi = 0; mi < 4; mi++)
#pragma unroll
                for (int nj = 0; nj < 8; nj++)
                    mma_fp16(acc[mi][nj], af[mi][0], af[mi][1], af[mi][2], af[mi][3],
                             bf[nj][0], bf[nj][1]);
        }
        __syncthreads();
        if (++buf == OSTG) buf = 0;
    }
#undef OPREF

#pragma unroll
    for (int mi = 0; mi < 4; mi++)
#pragma unroll
        for (int nj = 0; nj < 8; nj++) {
            int r = row0 + wm + mi * 16 + g;
            int c = col0 + wn + nj * 8 + 2 * t;
            *(float2*)(C + (size_t)r * N + c)       = make_float2(acc[mi][nj][0], acc[mi][nj][1]);
            *(float2*)(C + (size_t)(r + 8) * N + c) = make_float2(acc[mi][nj][2], acc[mi][nj][3]);
        }
}

// ---------------------------------------------------------------------------
// Flash attention (R13 version): 128 q-rows x 1 head, fp16 MMA,
// register-resident P, ldmatrix loads, 3-stage cp.async, ex2 softmax.
// ---------------------------------------------------------------------------
#define KP2 36
#define TILEW (64 * KP2)
#define NSTG 3
#define ATTN_SMEM (2 * NSTG * TILEW * (int)sizeof(uint32_t))

__global__ void __launch_bounds__(256) attn_kernel() {
    extern __shared__ uint32_t abuf[];
    uint32_t* Ks = abuf;
    uint32_t* Vs = abuf + NSTG * TILEW;

    const int tid = threadIdx.x;
    const int wid = tid >> 5, lane = tid & 31;
    const int g = lane >> 2, t = lane & 3;
    const int wm = wid * 16;
    const int h = blockIdx.y;
    const int kvh = h / GRP;
    const int bx = gridDim.x - 1 - blockIdx.x;
    const int m0 = bx * 128;

    const int rB = ((lane >> 4) & 1) * 8 + (lane & 7);
    const int cB = ((lane >> 3) & 1) * 4;
    const uint32_t ksb = (uint32_t)__cvta_generic_to_shared(Ks);
    const uint32_t vsb = (uint32_t)__cvta_generic_to_shared(Vs);

    const int pr0 = tid >> 3,          pc0 = tid & 7;
    const int pr1 = (tid + 256) >> 3,  pc1 = tid & 7;
    const __half* kbase = &g_kh[(size_t)kvh * DH];
    const __half* vbase = &g_vt[(size_t)kvh * DH * TT];

#define PREFETCH(jt_, buf_) do {                                               \
    const int nn = (jt_) * 64;                                                 \
    uint32_t kd = ksb + (uint32_t)(((buf_) * TILEW + pr0 * KP2 + pc0 * 4) * 4);\
    CP_ASYNC16(kd, kbase + (size_t)(nn + pr0) * (NKV * DH) + pc0 * 8);         \
    kd = ksb + (uint32_t)(((buf_) * TILEW + pr1 * KP2 + pc1 * 4) * 4);         \
    CP_ASYNC16(kd, kbase + (size_t)(nn + pr1) * (NKV * DH) + pc1 * 8);         \
    uint32_t vd = vsb + (uint32_t)(((buf_) * TILEW + pr0 * KP2 + pc0 * 4) * 4);\
    CP_ASYNC16(vd, vbase + (size_t)pr0 * TT + nn + pc0 * 8);                   \
    vd = vsb + (uint32_t)(((buf_) * TILEW + pr1 * KP2 + pc1 * 4) * 4);         \
    CP_ASYNC16(vd, vbase + (size_t)pr1 * TT + nn + pc1 * 8);                   \
    CP_COMMIT();                                                               \
} while (0)

    const int r0 = m0 + wm + g, r1 = r0 + 8;
    uint32_t qf[4][4];
    {
        const __half* q0 = &g_qh[(size_t)r0 * (NH * DH) + h * DH];
        const __half* q1 = &g_qh[(size_t)r1 * (NH * DH) + h * DH];
#pragma unroll
        for (int ks = 0; ks < 4; ks++) {
            qf[ks][0] = *(const uint32_t*)(q0 + ks * 16 + 2 * t);
            qf[ks][1] = *(const uint32_t*)(q1 + ks * 16 + 2 * t);
            qf[ks][2] = *(const uint32_t*)(q0 + ks * 16 + 8 + 2 * t);
            qf[ks][3] = *(const uint32_t*)(q1 + ks * 16 + 8 + 2 * t);
        }
    }

    float mr0 = -1e30f, mr1 = -1e30f, l0 = 0.f, l1 = 0.f;
    float o[8][4];
#pragma unroll
    for (int j = 0; j < 8; j++)
#pragma unroll
        for (int q = 0; q < 4; q++) o[j][q] = 0.f;

    const int ntiles = 2 * bx + 2;
    PREFETCH(0, 0);
    if (ntiles > 1) PREFETCH(1, 1);

    int buf = 0;
    for (int jt = 0; jt < ntiles; jt++) {
        const int n0 = jt * 64;
        if (jt + 2 < ntiles) {
            int pb = buf + 2; if (pb >= NSTG) pb -= NSTG;
            PREFETCH(jt + 2, pb);
            CP_WAIT(2);
        } else if (jt + 1 < ntiles) {
            CP_WAIT(1);
        } else {
            CP_WAIT(0);
        }
        __syncthreads();

        const uint32_t kb = ksb + (uint32_t)(buf * TILEW * 4);
        const uint32_t vb = vsb + (uint32_t)(buf * TILEW * 4);

        float s[8][4];
#pragma unroll
        for (int j = 0; j < 8; j++)
#pragma unroll
            for (int q = 0; q < 4; q++) s[j][q] = 0.f;
#pragma unroll
        for (int ks = 0; ks < 4; ks++) {
            const int kk2 = ks * 8;
#pragma unroll
            for (int njp = 0; njp < 4; njp++) {
                uint32_t b0, b1, b2, b3;
                uint32_t addr = kb + (uint32_t)(((njp * 16 + rB) * KP2 + kk2 + cB) * 4);
                ldsm4(b0, b1, b2, b3, addr);
                mma_fp16(s[2 * njp],     qf[ks][0], qf[ks][1], qf[ks][2], qf[ks][3], b0, b1);
                mma_fp16(s[2 * njp + 1], qf[ks][0], qf[ks][1], qf[ks][2], qf[ks][3], b2, b3);
            }
        }

        if (jt >= 2 * bx) {
#pragma unroll
            for (int nj = 0; nj < 8; nj++) {
                int c0 = n0 + nj * 8 + 2 * t;
                if (c0     > r0) s[nj][0] = -1e30f;
                if (c0 + 1 > r0) s[nj][1] = -1e30f;
                if (c0     > r1) s[nj][2] = -1e30f;
                if (c0 + 1 > r1) s[nj][3] = -1e30f;
            }
        }

        float mx0 = -1e30f, mx1 = -1e30f;
#pragma unroll
        for (int nj = 0; nj < 8; nj++) {
            mx0 = fmaxf(mx0, fmaxf(s[nj][0], s[nj][1]));
            mx1 = fmaxf(mx1, fmaxf(s[nj][2], s[nj][3]));
        }
        mx0 = fmaxf(mx0, __shfl_xor_sync(0xffffffffu, mx0, 1));
        mx0 = fmaxf(mx0, __shfl_xor_sync(0xffffffffu, mx0, 2));
        mx1 = fmaxf(mx1, __shfl_xor_sync(0xffffffffu, mx1, 1));
        mx1 = fmaxf(mx1, __shfl_xor_sync(0xffffffffu, mx1, 2));
        float nm0 = fmaxf(mr0, mx0), nm1 = fmaxf(mr1, mx1);
        float f0 = ex2(mr0 - nm0), f1 = ex2(mr1 - nm1);
        float ps0 = 0.f, ps1 = 0.f;
#pragma unroll
        for (int nj = 0; nj < 8; nj++) {
            s[nj][0] = ex2(s[nj][0] - nm0);
            s[nj][1] = ex2(s[nj][1] - nm0);
            s[nj][2] = ex2(s[nj][2] - nm1);
            s[nj][3] = ex2(s[nj][3] - nm1);
            ps0 += s[nj][0] + s[nj][1];
            ps1 += s[nj][2] + s[nj][3];
        }
        l0 = l0 * f0 + ps0; l1 = l1 * f1 + ps1;
        mr0 = nm0; mr1 = nm1;
#pragma unroll
        for (int nj = 0; nj < 8; nj++) {
            o[nj][0] *= f0; o[nj][1] *= f0;
            o[nj][2] *= f1; o[nj][3] *= f1;
        }

#pragma unroll
        for (int ks = 0; ks < 4; ks++) {
            uint32_t a0 = pack_half2(s[2 * ks][0],     s[2 * ks][1]);
            uint32_t a1 = pack_half2(s[2 * ks][2],     s[2 * ks][3]);
            uint32_t a2 = pack_half2(s[2 * ks + 1][0], s[2 * ks + 1][1]);
            uint32_t a3 = pack_half2(s[2 * ks + 1][2], s[2 * ks + 1][3]);
            const int kk2 = ks * 8;
#pragma unroll
            for (int njp = 0; njp < 4; njp++) {
                uint32_t b0, b1, b2, b3;
                uint32_t addr = vb + (uint32_t)(((njp * 16 + rB) * KP2 + kk2 + cB) * 4);
                ldsm4(b0, b1, b2, b3, addr);
                mma_fp16(o[2 * njp],     a0, a1, a2, a3, b0, b1);
                mma_fp16(o[2 * njp + 1], a0, a1, a2, a3, b2, b3);
            }
        }
        __syncthreads();
        if (++buf == NSTG) buf = 0;
    }

    l0 += __shfl_xor_sync(0xffffffffu, l0, 1);
    l0 += __shfl_xor_sync(0xffffffffu, l0, 2);
    l1 += __shfl_xor_sync(0xffffffffu, l1, 1);
    l1 += __shfl_xor_sync(0xffffffffu, l1, 2);
    float i0 = 1.f / l0, i1 = 1.f / l1;
#pragma unroll
    for (int nj = 0; nj < 8; nj++) {
        int c = nj * 8 + 2 * t;
        *(uint32_t*)&g_atth[(size_t)r0 * (NH * DH) + h * DH + c] =
            pack_half2(o[nj][0] * i0, o[nj][1] * i0);
        *(uint32_t*)&g_atth[(size_t)r1 * (NH * DH) + h * DH + c] =
            pack_half2(o[nj][2] * i1, o[nj][3] * i1);
    }
#undef PREFETCH
}

// ---------------------------------------------------------------------------
extern "C" void kernel_launch(void* const* d_in, const int* in_sizes, int n_in,
                              void* d_out, int out_size) {
    const float* x    = (const float*)d_in[0];
    const float* cosb = (const float*)d_in[1];
    const float* sinb = (const float*)d_in[2];
    const float* Wq   = (const float*)d_in[4];
    const float* Wk   = (const float*)d_in[5];
    const float* Wv   = (const float*)d_in[6];
    const float* Wo   = (const float*)d_in[7];
    float* out = (float*)d_out;

    cudaFuncSetAttribute(qkv_gemm, cudaFuncAttributeMaxDynamicSharedMemorySize, GEMM_SMEM);
    cudaFuncSetAttribute(o_gemm,   cudaFuncAttributeMaxDynamicSharedMemorySize, OGEMM_SMEM);
    cudaFuncSetAttribute(attn_kernel, cudaFuncAttributeMaxDynamicSharedMemorySize, ATTN_SMEM);

    tohalf_kernel<<<dim3(592, 5), 256>>>(x, Wq, Wk, Wv, Wo);

    qkv_gemm<<<dim3(24, 16), 256, GEMM_SMEM>>>(cosb, sinb);

    attn_kernel<<<dim3(TT / 128, NH), 256, ATTN_SMEM>>>();

    o_gemm<<<dim3(8, 16), 256, OGEMM_SMEM>>>(out);
}